// round 10
// baseline (speedup 1.0000x reference)
#include <cuda_runtime.h>
#include <cstdint>

#define FULL 0xffffffffu

constexpr int B_   = 16;
constexpr int GH_  = 64;
constexpr int GW_  = 64;
constexpr int ELEM = 85;
constexpr int T_   = 100;

constexpr int THREADS     = 256;        // 8 warps
constexpr int GX_PER_WARP = 8;          // 8 warps * 8 = 64 = GW_
constexpr int NBLOCKS     = B_ * GH_;   // 1024, one block per (b, gy)

__global__ void zero_out_kernel(float* out, int n) {
    int i = blockIdx.x * blockDim.x + threadIdx.x;
    if (i < n) out[i] = 0.f;
}

__global__ __launch_bounds__(THREADS, 5)
void yolo_loss_kernel(const float* __restrict__ yp,
                      const float* __restrict__ yt,
                      const float* __restrict__ tb,
                      float* __restrict__ out) {
    __shared__ float4 sbox[128];    // (minx, miny, maxx, maxy), padded
    __shared__ float  snarea[128];  // -(true area), padded

    const int bg   = blockIdx.x;     // b*64 + gy
    const int b    = bg >> 6;
    const int gy   = bg & 63;
    const int tid  = threadIdx.x;
    const int warp = tid >> 5;
    const int lane = tid & 31;

    // Stage true boxes (entries 100..127 degenerate: never trigger)
    if (tid < 128) {
        if (tid < T_) {
            const float4 v = ((const float4*)(tb + (size_t)b * T_ * 4))[tid];
            float x = v.x * (1.f / 64.f),   y = v.y * (1.f / 64.f);
            float w = v.z * (1.f / 1024.f), h = v.w * (1.f / 1024.f);
            sbox[tid]   = make_float4(x - 0.5f * w, y - 0.5f * h,
                                      x + 0.5f * w, y + 0.5f * h);
            snarea[tid] = -(w * h);
        } else {
            sbox[tid]   = make_float4(2e30f, 2e30f, -2e30f, -2e30f);
            snarea[tid] = -1e30f;
        }
    }
    __syncthreads();

    const int    gx0     = warp * GX_PER_WARP;
    const float  gyf     = (float)gy;
    const size_t rowbase = (((size_t)bg * GW_) + gx0) * 3 * ELEM;

    float acc = 0.f;

    #pragma unroll
    for (int a = 0; a < 3; ++a) {
        const float aw   = (a == 0) ? 116.f : ((a == 1) ? 156.f : 373.f);
        const float ah   = (a == 0) ? 90.f  : ((a == 1) ? 198.f : 326.f);
        const float awn  = aw * (1.f / 1024.f);
        const float ahn  = ah * (1.f / 1024.f);
        const float aan  = awn * ahn;

        const float* pp = yp + rowbase + a * ELEM;
        const float* tp = yt + rowbase + a * ELEM;

        #pragma unroll 1
        for (int i = 0; i < GX_PER_WARP; ++i, pp += 3 * ELEM, tp += 3 * ELEM) {
            // 170 floats per cell, coalesced
            float p0 = pp[lane];
            float p1 = pp[32 + lane];
            float p2 = (lane < 21) ? pp[64 + lane] : 0.f;
            float t0 = tp[lane];
            float t1 = tp[32 + lane];
            float t2 = (lane < 21) ? tp[64 + lane] : 0.f;

            // Broadcast the 10 header scalars
            float sx = __shfl_sync(FULL, p0, 0);
            float sy = __shfl_sync(FULL, p0, 1);
            float sw = __shfl_sync(FULL, p0, 2);
            float sh = __shfl_sync(FULL, p0, 3);
            float sc = __shfl_sync(FULL, p0, 4);
            float tx = __shfl_sync(FULL, t0, 0);
            float ty = __shfl_sync(FULL, t0, 1);
            float tw = __shfl_sync(FULL, t0, 2);
            float th = __shfl_sync(FULL, t0, 3);
            float om = __shfl_sync(FULL, t0, 4);

            // Pred box (uniform across lanes)
            float gxf  = (float)(gx0 + i);
            float pbx  = gxf + 1.f / (1.f + __expf(-sx));
            float pby  = gyf + 1.f / (1.f + __expf(-sy));
            float conf = 1.f / (1.f + __expf(-sc));
            float pwn  = __expf(sw) * awn;
            float phn  = __expf(sh) * ahn;
            float pxn  = pbx * (1.f / 64.f);
            float pyn  = pby * (1.f / 64.f);
            float pminx = pxn - 0.5f * pwn, pmaxx = pxn + 0.5f * pwn;
            float pminy = pyn - 0.5f * phn, pmaxy = pyn + 0.5f * phn;
            float pa   = pwn * phn;

            // max(iou) > 0.5  <=>  exists box: 3*inter - area > pa
            float best = -3e38f;
            #pragma unroll
            for (int k = 0; k < 4; ++k) {
                float4 bx = sbox[lane + k * 32];
                float  na = snarea[lane + k * 32];
                float iw = fminf(pmaxx, bx.z) - fmaxf(pminx, bx.x);
                float ih = fminf(pmaxy, bx.w) - fmaxf(pminy, bx.y);
                iw = fmaxf(iw, 0.f);
                ih = fmaxf(ih, 0.f);
                best = fmaxf(best, fmaf(3.f, iw * ih, na));
            }
            float ign = __ballot_sync(FULL, best > pa) ? 1.f : 0.f;

            // true-class argmax via REDUX on bit patterns (y_true >= 0)
            unsigned cb = __float_as_uint(t1);                 // classes 27..58
            if (lane >= 5) cb = max(cb, __float_as_uint(t0));  // classes 0..26
            if (lane < 21) cb = max(cb, __float_as_uint(t2));  // classes 59..79
            unsigned bvb = __reduce_max_sync(FULL, cb);

            // pred logit at the argmax: match + ballot + one shfl
            bool h0 = (lane >= 5) && (__float_as_uint(t0) == bvb);
            bool h1 = (__float_as_uint(t1) == bvb);
            bool h2 = (lane < 21) && (__float_as_uint(t2) == bvb);
            float mloc = h0 ? p0 : (h1 ? p1 : p2);
            unsigned ball = __ballot_sync(FULL, h0 | h1 | h2);
            float m = __shfl_sync(FULL, mloc, __ffs(ball) - 1);

            // logsumexp: fixed-point u32 REDUX sum (scale 2^21)
            float e = __expf(p1);
            if (lane >= 5) e += __expf(p0);
            if (lane < 21) e += __expf(p2);
            unsigned eu = __reduce_add_sync(FULL, (unsigned)(e * 2097152.f));
            float ce = __logf((float)eu * (1.f / 2097152.f)) - m;

            // wh_scale: 2 - exp(tw)*awn * exp(th)*ahn = 2 - aan*exp(tw+th)
            float whs = 2.f - aan * __expf(tw + th);

            // Factored xywh deltas: acc += (om*whs)^2 * sum(diff^2)
            float e0 = tx - pbx, e1 = ty - pby, e2 = tw - sw, e3 = th - sh;
            float s  = fmaf(e0, e0, fmaf(e1, e1, fmaf(e2, e2, e3 * e3)));
            float ow = om * whs;
            acc = fmaf(ow * ow, s, acc);

            float cd = fmaf(5.f * om, 1.f - conf, -conf);
            cd *= fmaf(om - 1.f, ign, 1.f);
            acc = fmaf(cd, cd, acc);

            float cld = om * ce;
            acc = fmaf(cld, cld, acc);
        }
    }

    // acc is warp-uniform (all terms from broadcast/fully-reduced values)
    if (lane == 0) atomicAdd(&out[b], acc);
}

extern "C" void kernel_launch(void* const* d_in, const int* in_sizes, int n_in,
                              void* d_out, int out_size) {
    // metadata order: input_image (unused), y_pred, y_true, true_boxes
    const float* yp = (const float*)d_in[1];
    const float* yt = (const float*)d_in[2];
    const float* tb = (const float*)d_in[3];
    float* out = (float*)d_out;

    zero_out_kernel<<<1, 32>>>(out, out_size);
    yolo_loss_kernel<<<NBLOCKS, THREADS>>>(yp, yt, tb, out);
}

// round 12
// speedup vs baseline: 1.5847x; 1.5847x over previous
#include <cuda_runtime.h>
#include <cstdint>

#define FULL 0xffffffffu

constexpr int B_   = 16;
constexpr int GH_  = 64;
constexpr int GW_  = 64;
constexpr int ELEM = 85;
constexpr int T_   = 100;

constexpr int THREADS     = 256;              // 8 warps
constexpr int GX_PER_WARP = 2;                // 8 warps * 2 = 16 gx = quarter row
constexpr int NBLOCKS     = B_ * GH_ * 4;     // 4096 quarter-rows

__global__ void zero_out_kernel(float* out, int n) {
    int i = blockIdx.x * blockDim.x + threadIdx.x;
    if (i < n) out[i] = 0.f;
}

__global__ __launch_bounds__(THREADS, 4)
void yolo_loss_kernel(const float* __restrict__ yp,
                      const float* __restrict__ yt,
                      const float* __restrict__ tb,
                      float* __restrict__ out) {
    __shared__ float swsum[8];

    const int blk  = blockIdx.x;
    const int bg   = blk >> 2;            // b*64 + gy
    const int q    = blk & 3;             // quarter of the row
    const int b    = bg >> 6;
    const int gy   = bg & 63;
    const int tid  = threadIdx.x;
    const int warp = tid >> 5;
    const int lane = tid & 31;

    // ── This lane's 4 true boxes in registers (batch-constant) ──
    float bminx[4], bminy[4], bmaxx[4], bmaxy[4], nArea[4];
    const float4* tbp = (const float4*)(tb + (size_t)b * T_ * 4);
    #pragma unroll
    for (int k = 0; k < 4; ++k) {
        int j = lane + k * 32;
        if (j < T_) {
            float4 v = tbp[j];
            float x = v.x * (1.f / 64.f),   y = v.y * (1.f / 64.f);
            float w = v.z * (1.f / 1024.f), h = v.w * (1.f / 1024.f);
            bminx[k] = x - 0.5f * w;  bmaxx[k] = x + 0.5f * w;
            bminy[k] = y - 0.5f * h;  bmaxy[k] = y + 0.5f * h;
            nArea[k] = -(w * h);
        } else {
            bminx[k] =  2e30f; bmaxx[k] = -2e30f;
            bminy[k] =  2e30f; bmaxy[k] = -2e30f;
            nArea[k] = -1e30f;
        }
    }

    const int    gx0     = q * 16 + warp * GX_PER_WARP;
    const float  gyf     = (float)gy;
    const size_t rowbase = (((size_t)bg * GW_) + gx0) * 3 * ELEM;

    float acc = 0.f;

    #pragma unroll
    for (int a = 0; a < 3; ++a) {
        const float aw   = (a == 0) ? 116.f : ((a == 1) ? 156.f : 373.f);
        const float ah   = (a == 0) ? 90.f  : ((a == 1) ? 198.f : 326.f);
        const float awn  = aw * (1.f / 1024.f);
        const float ahn  = ah * (1.f / 1024.f);
        const float aan  = awn * ahn;

        const float* pp = yp + rowbase + a * ELEM;
        const float* tp = yt + rowbase + a * ELEM;

        #pragma unroll 1
        for (int i = 0; i < GX_PER_WARP; ++i, pp += 3 * ELEM, tp += 3 * ELEM) {
            // Per-lane vectors (coalesced) — issue first for MLP
            float p0 = pp[lane];
            float p1 = pp[32 + lane];
            float p2 = (lane < 21) ? pp[64 + lane] : 0.f;
            float t0 = tp[lane];
            float t1 = tp[32 + lane];
            float t2 = (lane < 21) ? tp[64 + lane] : 0.f;

            // Header scalars via uniform-address loads (L1-hit, 1 wf each;
            // no dependency on the vector loads -> uniform math starts early)
            float sx = pp[0], sy = pp[1], sw = pp[2], sh = pp[3], sc = pp[4];
            float tx = tp[0], ty = tp[1], tw = tp[2], th = tp[3], om = tp[4];

            // Pred box (uniform across lanes)
            float gxf  = (float)(gx0 + i);
            float pbx  = gxf + 1.f / (1.f + __expf(-sx));
            float pby  = gyf + 1.f / (1.f + __expf(-sy));
            float conf = 1.f / (1.f + __expf(-sc));
            float pwn  = __expf(sw) * awn;
            float phn  = __expf(sh) * ahn;
            float pxn  = pbx * (1.f / 64.f);
            float pyn  = pby * (1.f / 64.f);
            float pminx = pxn - 0.5f * pwn, pmaxx = pxn + 0.5f * pwn;
            float pminy = pyn - 0.5f * phn, pmaxy = pyn + 0.5f * phn;
            float pa   = pwn * phn;

            // max(iou) > 0.5  <=>  exists box: 3*inter - area > pa
            float best = -3e38f;
            #pragma unroll
            for (int k = 0; k < 4; ++k) {
                float iw = fminf(pmaxx, bmaxx[k]) - fmaxf(pminx, bminx[k]);
                float ih = fminf(pmaxy, bmaxy[k]) - fmaxf(pminy, bminy[k]);
                iw = fmaxf(iw, 0.f);
                ih = fmaxf(ih, 0.f);
                best = fmaxf(best, fmaf(3.f, iw * ih, nArea[k]));
            }
            float ign = __ballot_sync(FULL, best > pa) ? 1.f : 0.f;

            // true-class max (value only, no index tracking)
            float bv = t1;                           // classes 27..58: always valid
            if (lane >= 5) bv = fmaxf(bv, t0);
            if (lane < 21) bv = fmaxf(bv, t2);
            #pragma unroll
            for (int o = 16; o; o >>= 1)
                bv = fmaxf(bv, __shfl_xor_sync(FULL, bv, o));

            // pred logit at the argmax: match + ballot + one shfl
            bool h0 = (lane >= 5) && (t0 == bv);
            bool h1 = (t1 == bv);
            bool h2 = (lane < 21) && (t2 == bv);
            float mloc = h0 ? p0 : (h1 ? p1 : p2);
            unsigned ball = __ballot_sync(FULL, h0 | h1 | h2);
            float m = __shfl_sync(FULL, mloc, __ffs(ball) - 1);

            // logsumexp over 80 pred-class logits (float butterfly)
            float e = __expf(p1);
            if (lane >= 5) e += __expf(p0);
            if (lane < 21) e += __expf(p2);
            #pragma unroll
            for (int o = 16; o; o >>= 1)
                e += __shfl_xor_sync(FULL, e, o);
            float ce = __logf(e) - m;

            // wh_scale: 2 - aan*exp(tw+th)
            float whs = 2.f - aan * __expf(tw + th);

            // Factored xywh deltas: acc += (om*whs)^2 * sum(diff^2)
            float e0 = tx - pbx, e1 = ty - pby, e2 = tw - sw, e3 = th - sh;
            float s  = fmaf(e0, e0, fmaf(e1, e1, fmaf(e2, e2, e3 * e3)));
            float ow = om * whs;
            acc = fmaf(ow * ow, s, acc);

            float cd = fmaf(5.f * om, 1.f - conf, -conf);
            cd *= fmaf(om - 1.f, ign, 1.f);
            acc = fmaf(cd, cd, acc);

            float cld = om * ce;
            acc = fmaf(cld, cld, acc);
        }
    }

    // acc is warp-uniform; reduce 8 warps in smem, one atomic per block
    if (lane == 0) swsum[warp] = acc;
    __syncthreads();
    if (tid == 0) {
        float ssum = 0.f;
        #pragma unroll
        for (int w = 0; w < 8; ++w) ssum += swsum[w];
        atomicAdd(&out[b], ssum);
    }
}

extern "C" void kernel_launch(void* const* d_in, const int* in_sizes, int n_in,
                              void* d_out, int out_size) {
    // metadata order: input_image (unused), y_pred, y_true, true_boxes
    const float* yp = (const float*)d_in[1];
    const float* yt = (const float*)d_in[2];
    const float* tb = (const float*)d_in[3];
    float* out = (float*)d_out;

    zero_out_kernel<<<1, 32>>>(out, out_size);
    yolo_loss_kernel<<<NBLOCKS, THREADS>>>(yp, yt, tb, out);
}

// round 16
// speedup vs baseline: 1.6000x; 1.0097x over previous
#include <cuda_runtime.h>
#include <cstdint>

#define FULL 0xffffffffu

constexpr int B_   = 16;
constexpr int GH_  = 64;
constexpr int GW_  = 64;
constexpr int ELEM = 85;
constexpr int T_   = 100;

constexpr int THREADS     = 256;              // 8 warps
constexpr int GX_PER_WARP = 2;                // 8 warps * 2 = 16 gx = quarter row
constexpr int NBLOCKS     = B_ * GH_ * 4;     // 4096 quarter-rows

__global__ void zero_out_kernel(float* out, int n) {
    int i = blockIdx.x * blockDim.x + threadIdx.x;
    if (i < n) out[i] = 0.f;
}

__global__ __launch_bounds__(THREADS, 5)
void yolo_loss_kernel(const float* __restrict__ yp,
                      const float* __restrict__ yt,
                      const float* __restrict__ tb,
                      float* __restrict__ out) {
    __shared__ float swsum[8];

    const int blk  = blockIdx.x;
    const int bg   = blk >> 2;            // b*64 + gy
    const int q    = blk & 3;             // quarter of the row
    const int b    = bg >> 6;
    const int gy   = bg & 63;
    const int tid  = threadIdx.x;
    const int warp = tid >> 5;
    const int lane = tid & 31;

    const float4* tbp = (const float4*)(tb + (size_t)b * T_ * 4);

    // ── One-time per warp: bounding box of all 100 true boxes + min area ──
    // (fp min/max are exact; used only for a conservative warp-uniform screen)
    float bbminx = 2e30f, bbminy = 2e30f, bbmaxx = -2e30f, bbmaxy = -2e30f;
    float amin = 2e30f;
    #pragma unroll
    for (int k = 0; k < 4; ++k) {
        int j = lane + k * 32;
        if (j < T_) {
            float4 v = tbp[j];
            float x = v.x * (1.f / 64.f),   y = v.y * (1.f / 64.f);
            float w = v.z * (1.f / 1024.f), h = v.w * (1.f / 1024.f);
            bbminx = fminf(bbminx, x - 0.5f * w);
            bbmaxx = fmaxf(bbmaxx, x + 0.5f * w);
            bbminy = fminf(bbminy, y - 0.5f * h);
            bbmaxy = fmaxf(bbmaxy, y + 0.5f * h);
            amin   = fminf(amin, w * h);
        }
    }
    #pragma unroll
    for (int o = 16; o; o >>= 1) {
        bbminx = fminf(bbminx, __shfl_xor_sync(FULL, bbminx, o));
        bbmaxx = fmaxf(bbmaxx, __shfl_xor_sync(FULL, bbmaxx, o));
        bbminy = fminf(bbminy, __shfl_xor_sync(FULL, bbminy, o));
        bbmaxy = fmaxf(bbmaxy, __shfl_xor_sync(FULL, bbmaxy, o));
        amin   = fminf(amin,   __shfl_xor_sync(FULL, amin,   o));
    }

    const int    gx0     = q * 16 + warp * GX_PER_WARP;
    const float  gyf     = (float)gy;
    const size_t rowbase = (((size_t)bg * GW_) + gx0) * 3 * ELEM;

    float acc = 0.f;

    #pragma unroll
    for (int a = 0; a < 3; ++a) {
        const float aw   = (a == 0) ? 116.f : ((a == 1) ? 156.f : 373.f);
        const float ah   = (a == 0) ? 90.f  : ((a == 1) ? 198.f : 326.f);
        const float awn  = aw * (1.f / 1024.f);
        const float ahn  = ah * (1.f / 1024.f);
        const float aan  = awn * ahn;

        const float* pp = yp + rowbase + a * ELEM;
        const float* tp = yt + rowbase + a * ELEM;

        #pragma unroll 1
        for (int i = 0; i < GX_PER_WARP; ++i, pp += 3 * ELEM, tp += 3 * ELEM) {
            // Per-lane vectors (coalesced) — issue first for MLP
            float p0 = pp[lane];
            float p1 = pp[32 + lane];
            float p2 = (lane < 21) ? pp[64 + lane] : 0.f;
            float t0 = tp[lane];
            float t1 = tp[32 + lane];
            float t2 = (lane < 21) ? tp[64 + lane] : 0.f;

            // Header scalars via uniform-address loads (independent of vectors)
            float sx = pp[0], sy = pp[1], sw = pp[2], sh = pp[3], sc = pp[4];
            float tx = tp[0], ty = tp[1], tw = tp[2], th = tp[3], om = tp[4];

            // Pred box (uniform across lanes)
            float gxf  = (float)(gx0 + i);
            float pbx  = gxf + 1.f / (1.f + __expf(-sx));
            float pby  = gyf + 1.f / (1.f + __expf(-sy));
            float conf = 1.f / (1.f + __expf(-sc));
            float pwn  = __expf(sw) * awn;
            float phn  = __expf(sh) * ahn;
            float pxn  = pbx * (1.f / 64.f);
            float pyn  = pby * (1.f / 64.f);
            float pminx = pxn - 0.5f * pwn, pmaxx = pxn + 0.5f * pwn;
            float pminy = pyn - 0.5f * phn, pmaxy = pyn + 0.5f * phn;
            float pa   = pwn * phn;

            // Conservative screen: inter with the union bbox bounds every
            // per-box inter; amin bounds every per-box area. Monotone fp ops
            // => if the screen fails, no box can satisfy 3*inter-area > pa.
            float ign = 0.f;
            {
                float iw = fmaxf(fminf(pmaxx, bbmaxx) - fmaxf(pminx, bbminx), 0.f);
                float ih = fmaxf(fminf(pmaxy, bbmaxy) - fmaxf(pminy, bbminy), 0.f);
                if (fmaf(3.f, iw * ih, -amin) > pa) {   // warp-uniform branch (rare)
                    float best = -3e38f;
                    #pragma unroll
                    for (int k = 0; k < 4; ++k) {
                        int j = lane + k * 32;
                        float4 v = (j < T_) ? tbp[j]
                                            : make_float4(1e30f, 1e30f, -1e30f, -1e30f);
                        float x = v.x * (1.f / 64.f),   y = v.y * (1.f / 64.f);
                        float w = v.z * (1.f / 1024.f), h = v.w * (1.f / 1024.f);
                        float iw2 = fminf(pmaxx, x + 0.5f * w) - fmaxf(pminx, x - 0.5f * w);
                        float ih2 = fminf(pmaxy, y + 0.5f * h) - fmaxf(pminy, y - 0.5f * h);
                        iw2 = fmaxf(iw2, 0.f);
                        ih2 = fmaxf(ih2, 0.f);
                        float sc2 = fmaf(3.f, iw2 * ih2, -(w * h));
                        best = (j < T_) ? fmaxf(best, sc2) : best;
                    }
                    ign = __ballot_sync(FULL, best > pa) ? 1.f : 0.f;
                }
            }

            // true-class max (value only, no index tracking)
            float bv = t1;                           // classes 27..58: always valid
            if (lane >= 5) bv = fmaxf(bv, t0);
            if (lane < 21) bv = fmaxf(bv, t2);
            #pragma unroll
            for (int o = 16; o; o >>= 1)
                bv = fmaxf(bv, __shfl_xor_sync(FULL, bv, o));

            // pred logit at the argmax: match + ballot + one shfl
            bool h0 = (lane >= 5) && (t0 == bv);
            bool h1 = (t1 == bv);
            bool h2 = (lane < 21) && (t2 == bv);
            float mloc = h0 ? p0 : (h1 ? p1 : p2);
            unsigned ball = __ballot_sync(FULL, h0 | h1 | h2);
            float m = __shfl_sync(FULL, mloc, __ffs(ball) - 1);

            // logsumexp over 80 pred-class logits (float butterfly)
            float e = __expf(p1);
            if (lane >= 5) e += __expf(p0);
            if (lane < 21) e += __expf(p2);
            #pragma unroll
            for (int o = 16; o; o >>= 1)
                e += __shfl_xor_sync(FULL, e, o);
            float ce = __logf(e) - m;

            // wh_scale: 2 - aan*exp(tw+th)
            float whs = 2.f - aan * __expf(tw + th);

            // Factored xywh deltas: acc += (om*whs)^2 * sum(diff^2)
            float e0 = tx - pbx, e1 = ty - pby, e2 = tw - sw, e3 = th - sh;
            float s  = fmaf(e0, e0, fmaf(e1, e1, fmaf(e2, e2, e3 * e3)));
            float ow = om * whs;
            acc = fmaf(ow * ow, s, acc);

            float cd = fmaf(5.f * om, 1.f - conf, -conf);
            cd *= fmaf(om - 1.f, ign, 1.f);
            acc = fmaf(cd, cd, acc);

            float cld = om * ce;
            acc = fmaf(cld, cld, acc);
        }
    }

    // acc is warp-uniform; reduce 8 warps in smem, one atomic per block
    if (lane == 0) swsum[warp] = acc;
    __syncthreads();
    if (tid == 0) {
        float ssum = 0.f;
        #pragma unroll
        for (int w = 0; w < 8; ++w) ssum += swsum[w];
        atomicAdd(&out[b], ssum);
    }
}

extern "C" void kernel_launch(void* const* d_in, const int* in_sizes, int n_in,
                              void* d_out, int out_size) {
    // metadata order: input_image (unused), y_pred, y_true, true_boxes
    const float* yp = (const float*)d_in[1];
    const float* yt = (const float*)d_in[2];
    const float* tb = (const float*)d_in[3];
    float* out = (float*)d_out;

    zero_out_kernel<<<1, 32>>>(out, out_size);
    yolo_loss_kernel<<<NBLOCKS, THREADS>>>(yp, yt, tb, out);
}

// round 17
// speedup vs baseline: 1.8607x; 1.1629x over previous
#include <cuda_runtime.h>
#include <cstdint>

#define FULL 0xffffffffu

constexpr int B_   = 16;
constexpr int GH_  = 64;
constexpr int GW_  = 64;
constexpr int ELEM = 85;
constexpr int T_   = 100;

constexpr int THREADS          = 128;                 // 4 warps
constexpr int CPW              = 32;                  // cells per warp
constexpr int CELLS_PER_BLOCK  = 4 * CPW;             // 128
constexpr int TOTAL_CELLS      = B_ * GH_ * GW_ * 3;  // 196608
constexpr int NBLOCKS          = TOTAL_CELLS / CELLS_PER_BLOCK;        // 1536
constexpr int BLOCKS_PER_BATCH = (GH_ * GW_ * 3) / CELLS_PER_BLOCK;    // 96

__global__ void zero_out_kernel(float* out, int n) {
    int i = blockIdx.x * blockDim.x + threadIdx.x;
    if (i < n) out[i] = 0.f;
}

__global__ __launch_bounds__(THREADS, 8)
void yolo_loss_kernel(const float* __restrict__ yp,
                      const float* __restrict__ yt,
                      const float* __restrict__ tb,
                      float* __restrict__ out) {
    __shared__ float4 sbox[128];    // (minx,miny,maxx,maxy), padded
    __shared__ float  sarea[128];   // true box area, padded (+inf)
    __shared__ float  swsum[4];

    const int blk  = blockIdx.x;
    const int tid  = threadIdx.x;
    const int warp = tid >> 5;
    const int lane = tid & 31;
    const int b    = blk / BLOCKS_PER_BATCH;

    // ── Stage true boxes (padded entries never extend the union / lower amin) ──
    {
        if (tid < T_) {
            float4 v = ((const float4*)(tb + (size_t)b * T_ * 4))[tid];
            float x = v.x * (1.f / 64.f),   y = v.y * (1.f / 64.f);
            float w = v.z * (1.f / 1024.f), h = v.w * (1.f / 1024.f);
            sbox[tid]  = make_float4(x - 0.5f * w, y - 0.5f * h,
                                     x + 0.5f * w, y + 0.5f * h);
            sarea[tid] = w * h;
        } else {
            sbox[tid]  = make_float4(2e30f, 2e30f, -2e30f, -2e30f);
            sarea[tid] = 2e30f;
        }
    }
    __syncthreads();

    // ── Per-warp: bounding box of all true boxes + min area (exact fp bounds) ──
    float bbminx = 2e30f, bbminy = 2e30f, bbmaxx = -2e30f, bbmaxy = -2e30f;
    float amin = 2e30f;
    #pragma unroll
    for (int k = 0; k < 4; ++k) {
        float4 v = sbox[lane + k * 32];
        bbminx = fminf(bbminx, v.x);
        bbminy = fminf(bbminy, v.y);
        bbmaxx = fmaxf(bbmaxx, v.z);
        bbmaxy = fmaxf(bbmaxy, v.w);
        amin   = fminf(amin, sarea[lane + k * 32]);
    }
    #pragma unroll
    for (int o = 16; o; o >>= 1) {
        bbminx = fminf(bbminx, __shfl_xor_sync(FULL, bbminx, o));
        bbminy = fminf(bbminy, __shfl_xor_sync(FULL, bbminy, o));
        bbmaxx = fmaxf(bbmaxx, __shfl_xor_sync(FULL, bbmaxx, o));
        bbmaxy = fmaxf(bbmaxy, __shfl_xor_sync(FULL, bbmaxy, o));
        amin   = fminf(amin,   __shfl_xor_sync(FULL, amin,   o));
    }

    const int c0 = blk * CELLS_PER_BLOCK + warp * CPW;

    // ════ Phase B: lane-parallel header math — lane <-> cell c0+lane ════
    const int   c   = c0 + lane;
    const int   a   = c % 3;
    const int   g   = c / 3;
    const float gxf = (float)(g & 63);
    const float gyf = (float)((g >> 6) & 63);
    const float aw  = (a == 0) ? 116.f : ((a == 1) ? 156.f : 373.f);
    const float ah  = (a == 0) ? 90.f  : ((a == 1) ? 198.f : 326.f);
    const float awn = aw * (1.f / 1024.f);
    const float ahn = ah * (1.f / 1024.f);
    const float aan = awn * ahn;

    const float* hp = yp + (size_t)c * ELEM;
    const float* ht = yt + (size_t)c * ELEM;
    float sx = hp[0], sy = hp[1], sw = hp[2], sh = hp[3], sc = hp[4];
    float tx = ht[0], ty = ht[1], tw = ht[2], th = ht[3], om = ht[4];

    float pbx  = gxf + 1.f / (1.f + __expf(-sx));
    float pby  = gyf + 1.f / (1.f + __expf(-sy));
    float conf = 1.f / (1.f + __expf(-sc));
    float pwn  = __expf(sw) * awn;
    float phn  = __expf(sh) * ahn;
    float pxn  = pbx * (1.f / 64.f);
    float pyn  = pby * (1.f / 64.f);
    float pminx = pxn - 0.5f * pwn, pmaxx = pxn + 0.5f * pwn;
    float pminy = pyn - 0.5f * phn, pmaxy = pyn + 0.5f * phn;
    float pa   = pwn * phn;

    // Conservative per-lane screen (monotone fp => exact when it skips);
    // exact per-lane 100-box fallback otherwise (rare).
    float ign = 0.f;
    {
        float iw = fmaxf(fminf(pmaxx, bbmaxx) - fmaxf(pminx, bbminx), 0.f);
        float ih = fmaxf(fminf(pmaxy, bbmaxy) - fmaxf(pminy, bbminy), 0.f);
        unsigned need = __ballot_sync(FULL, fmaf(3.f, iw * ih, -amin) > pa);
        if (need) {
            if ((need >> lane) & 1u) {
                float best = -3e38f;
                for (int j = 0; j < T_; ++j) {
                    float4 bx = sbox[j];
                    float iw2 = fmaxf(fminf(pmaxx, bx.z) - fmaxf(pminx, bx.x), 0.f);
                    float ih2 = fmaxf(fminf(pmaxy, bx.w) - fmaxf(pminy, bx.y), 0.f);
                    best = fmaxf(best, fmaf(3.f, iw2 * ih2, -sarea[j]));
                }
                ign = (best > pa) ? 1.f : 0.f;
            }
        }
    }

    // Lane-local delta terms (xywh + conf)
    float whs = 2.f - aan * __expf(tw + th);
    float ow  = om * whs;
    float d0 = tx - pbx, d1 = ty - pby, d2 = tw - sw, d3 = th - sh;
    float s  = fmaf(d0, d0, fmaf(d1, d1, fmaf(d2, d2, d3 * d3)));
    float acc = ow * ow * s;
    float cd = fmaf(5.f * om, 1.f - conf, -conf);
    cd *= fmaf(om - 1.f, ign, 1.f);
    acc = fmaf(cd, cd, acc);

    // ════ Phase A: warp-per-cell class cross-entropy ════
    const float* pp = yp + (size_t)c0 * ELEM;
    const float* tp = yt + (size_t)c0 * ELEM;
    float ce_l = 0.f;

    #pragma unroll 1
    for (int i = 0; i < CPW; ++i, pp += ELEM, tp += ELEM) {
        float p0 = pp[lane];
        float p1 = pp[32 + lane];
        float p2 = (lane < 21) ? pp[64 + lane] : 0.f;
        float t0 = tp[lane];
        float t1 = tp[32 + lane];
        float t2 = (lane < 21) ? tp[64 + lane] : 0.f;

        // true-class max (value only)
        float bv = t1;                        // classes 27..58: always valid
        if (lane >= 5) bv = fmaxf(bv, t0);
        if (lane < 21) bv = fmaxf(bv, t2);
        #pragma unroll
        for (int o = 16; o; o >>= 1)
            bv = fmaxf(bv, __shfl_xor_sync(FULL, bv, o));

        // pred logit at argmax: match + ballot + one shfl
        bool h0 = (lane >= 5) && (t0 == bv);
        bool h1 = (t1 == bv);
        bool h2 = (lane < 21) && (t2 == bv);
        float mloc = h0 ? p0 : (h1 ? p1 : p2);
        unsigned ball = __ballot_sync(FULL, h0 | h1 | h2);
        float m = __shfl_sync(FULL, mloc, __ffs(ball) - 1);

        // logsumexp over 80 pred-class logits
        float e = __expf(p1);
        if (lane >= 5) e += __expf(p0);
        if (lane < 21) e += __expf(p2);
        #pragma unroll
        for (int o = 16; o; o >>= 1)
            e += __shfl_xor_sync(FULL, e, o);

        float ce = __logf(e) - m;
        if (lane == i) ce_l = ce;   // deposit into owning lane
    }

    float cld = om * ce_l;
    acc = fmaf(cld, cld, acc);

    // ── Reduce: warp butterfly, then 4 warps via smem, one atomic ──
    #pragma unroll
    for (int o = 16; o; o >>= 1)
        acc += __shfl_xor_sync(FULL, acc, o);
    if (lane == 0) swsum[warp] = acc;
    __syncthreads();
    if (tid == 0)
        atomicAdd(&out[b], swsum[0] + swsum[1] + swsum[2] + swsum[3]);
}

extern "C" void kernel_launch(void* const* d_in, const int* in_sizes, int n_in,
                              void* d_out, int out_size) {
    // metadata order: input_image (unused), y_pred, y_true, true_boxes
    const float* yp = (const float*)d_in[1];
    const float* yt = (const float*)d_in[2];
    const float* tb = (const float*)d_in[3];
    float* out = (float*)d_out;

    zero_out_kernel<<<1, 32>>>(out, out_size);
    yolo_loss_kernel<<<NBLOCKS, THREADS>>>(yp, yt, tb, out);
}